// round 9
// baseline (speedup 1.0000x reference)
#include <cuda_runtime.h>
#include <math.h>
#include <stdint.h>

#define EPS 1e-5f

__device__ __forceinline__ float to_tf32(float x) {
    uint32_t r;
    asm("cvt.rna.tf32.f32 %0, %1;" : "=r"(r) : "f"(x));
    return __uint_as_float(r);
}

// ---------------- static scratch ----------------
__device__ float g_t1[2*128*64*64];
__device__ float g_t2[2*128*64*64];
__device__ float g_g2[2*128*128*128];
__device__ float g_K1[2*9*128*128];
__device__ float g_M1[2*9*64*64*64];
__device__ float g_y1[2*64*128*128];
__device__ float g_g1[2*64*256*256];
__device__ float g_K2[2*9*256*256];
__device__ float g_M2[2*9*32*128*128];
__device__ float g_y2[2*32*256*256];
__device__ float g_na[1024];
__device__ float g_nc[1024];

// ---------------- instance stats + fused coefficient ----------------
template<int DMODE>
__global__ void stats_coef(const float* __restrict__ x, int HW,
                           float* __restrict__ na, float* __restrict__ nc) {
    int bc = blockIdx.x;
    const float* p = x + (size_t)bc * HW;
    float s = 0.f, ss = 0.f;
    for (int i = threadIdx.x; i < HW; i += blockDim.x) {
        float v = p[i]; s += v; ss += v * v;
    }
    __shared__ float sh0[32], sh1[32];
    for (int o = 16; o; o >>= 1) {
        s  += __shfl_down_sync(0xffffffffu, s, o);
        ss += __shfl_down_sync(0xffffffffu, ss, o);
    }
    int wid = threadIdx.x >> 5, lid = threadIdx.x & 31;
    if (lid == 0) { sh0[wid] = s; sh1[wid] = ss; }
    __syncthreads();
    if (wid == 0) {
        int nw = blockDim.x >> 5;
        s  = (lid < nw) ? sh0[lid] : 0.f;
        ss = (lid < nw) ? sh1[lid] : 0.f;
        for (int o = 16; o; o >>= 1) {
            s  += __shfl_down_sync(0xffffffffu, s, o);
            ss += __shfl_down_sync(0xffffffffu, ss, o);
        }
        if (lid == 0) {
            float m = s / (float)HW;
            float v = ss / (float)HW - m * m;
            if (DMODE == 0) {
                float r = rsqrtf(v + EPS);
                na[bc] = r; nc[bc] = -m * r;
            } else {
                float r1 = rsqrtf(v + EPS);
                float a1 = 1.f + r1, c1 = -m * r1;
                float m2 = a1 * m + c1;
                float v2 = a1 * a1 * v;
                float r2 = rsqrtf(v2 + EPS);
                na[bc] = a1 * (1.f + r2);
                nc[bc] = c1 * (1.f + r2) - m2 * r2;
            }
        }
    }
}

// ---------------- tf32 mma implicit-GEMM 3x3 conv, pad 1 ----------------
// 256 thr = 8 warps; block tile 64 co x 64 px (one row strip); K = Ci*9 tap-major.
// grid (Hs*Ws/64, Co/64, B). w layout (Co,Ci,3,3). Optional per-(b,ci) input affine.
__global__ void __launch_bounds__(256) conv3x3_mma(
        const float* __restrict__ in, const float* __restrict__ w,
        const float* __restrict__ bias, float* __restrict__ out,
        int Ci, int Co, int Hs, int Ws,
        const float* __restrict__ na, const float* __restrict__ nc) {
    const int KC = 8;
    __shared__ float Xs[KC][3][72];     // k-stride 216 floats -> conflict-free frag loads
    __shared__ float Wss[9][KC][72];    // k-stride 72 -> conflict-free

    int tprow = Ws >> 6;
    int t = blockIdx.x;
    int y = t / tprow;
    int x0 = (t - y * tprow) << 6;
    int co0 = blockIdx.y << 6;
    int b = blockIdx.z;
    int tid = threadIdx.x;
    int lane = tid & 31, wid = tid >> 5;
    int cb = (wid >> 1) << 4;   // warp co offset: 0,16,32,48
    int pxb = (wid & 1) << 5;   // warp px offset: 0,32
    int tig = lane & 3, grp = lane >> 2;

    float acc[4][4] = {};
    const float* inb = in + (size_t)b * Ci * Hs * Ws;
    int HsWs = Hs * Ws;

    for (int ci0 = 0; ci0 < Ci; ci0 += KC) {
        // stage input strip (3 rows x 66 cols per channel), zero-padded, affine fused
        for (int e = tid; e < KC * 3 * 66; e += 256) {
            int k = e / 198, rem = e - k * 198;
            int r = rem / 66, c = rem - r * 66;
            int yy = y + r - 1, xx = x0 + c - 1;
            float v = 0.f;
            if ((unsigned)yy < (unsigned)Hs && (unsigned)xx < (unsigned)Ws) {
                v = inb[(size_t)(ci0 + k) * HsWs + yy * Ws + xx];
                if (na) v = fmaf(na[b * Ci + ci0 + k], v, nc[b * Ci + ci0 + k]);
            }
            Xs[k][r][c] = to_tf32(v);
        }
        // stage weights: Wss[tap][k][co]
        for (int e = tid; e < 9 * KC * 64; e += 256) {
            int tap = e / (KC * 64), rem = e - tap * KC * 64;
            int k = rem >> 6, co = rem & 63;
            Wss[tap][k][co] = to_tf32(w[((size_t)(co0 + co) * Ci + ci0 + k) * 9 + tap]);
        }
        __syncthreads();

        #pragma unroll
        for (int dy = 0; dy < 3; dy++)
            #pragma unroll
            for (int dx = 0; dx < 3; dx++) {
                int tap = dy * 3 + dx;
                uint32_t a0 = __float_as_uint(Wss[tap][tig][cb + grp]);
                uint32_t a1 = __float_as_uint(Wss[tap][tig][cb + grp + 8]);
                uint32_t a2 = __float_as_uint(Wss[tap][tig + 4][cb + grp]);
                uint32_t a3 = __float_as_uint(Wss[tap][tig + 4][cb + grp + 8]);
                #pragma unroll
                for (int j = 0; j < 4; j++) {
                    int px = pxb + j * 8 + grp;
                    uint32_t b0 = __float_as_uint(Xs[tig][dy][px + dx]);
                    uint32_t b1 = __float_as_uint(Xs[tig + 4][dy][px + dx]);
                    asm volatile(
                        "mma.sync.aligned.m16n8k8.row.col.f32.tf32.tf32.f32 "
                        "{%0,%1,%2,%3}, {%4,%5,%6,%7}, {%8,%9}, {%0,%1,%2,%3};"
                        : "+f"(acc[j][0]), "+f"(acc[j][1]), "+f"(acc[j][2]), "+f"(acc[j][3])
                        : "r"(a0), "r"(a1), "r"(a2), "r"(a3), "r"(b0), "r"(b1));
                }
            }
        __syncthreads();
    }

    int coA = co0 + cb + grp, coB = coA + 8;
    float bvA = bias[coA], bvB = bias[coB];
    #pragma unroll
    for (int j = 0; j < 4; j++) {
        int x = x0 + pxb + j * 8 + tig * 2;
        float* pA = out + (((size_t)b * Co + coA) * Hs + y) * Ws + x;
        float* pB = out + (((size_t)b * Co + coB) * Hs + y) * Ws + x;
        *(float2*)pA = make_float2(acc[j][0] + bvA, acc[j][1] + bvA);
        *(float2*)pB = make_float2(acc[j][2] + bvB, acc[j][3] + bvB);
    }
}

// ---------------- scalar 3x3 conv (final 3-channel layer only) ----------------
template<int CO_BLK, int PXH, bool BIAS>
__global__ void __launch_bounds__(128) conv3x3_v2(
        const float* __restrict__ in, const float* __restrict__ w,
        const float* __restrict__ bias, float* __restrict__ out,
        int Ci, int Co, int Hs, int Ws,
        const float* __restrict__ na, const float* __restrict__ nc) {
    const int TW = 32, TH = 8 * PXH;
    int tiles_x = Ws / TW;
    int tx0 = (blockIdx.x % tiles_x) * TW;
    int ty0 = (blockIdx.x / tiles_x) * TH;
    int co0 = blockIdx.y * CO_BLK;
    int b = blockIdx.z;
    int lx = threadIdx.x, ly = threadIdx.y;
    int tid = ly * 16 + lx;

    __shared__ float xs[TH + 2][TW + 4];
    __shared__ float ws_s[CO_BLK][9];

    float acc[CO_BLK][PXH][2];
    #pragma unroll
    for (int u = 0; u < CO_BLK; u++)
        #pragma unroll
        for (int r = 0; r < PXH; r++) { acc[u][r][0] = 0.f; acc[u][r][1] = 0.f; }

    const float* inb = in + (size_t)b * Ci * Hs * Ws;
    for (int ci = 0; ci < Ci; ci++) {
        const float* inc = inb + (size_t)ci * Hs * Ws;
        float aa = 1.f, cc0 = 0.f;
        if (na) { aa = na[b * Ci + ci]; cc0 = nc[b * Ci + ci]; }
        #pragma unroll 4
        for (int i = tid; i < (TH + 2) * (TW + 2); i += 128) {
            int r = i / (TW + 2), c = i % (TW + 2);
            int gy = ty0 + r - 1, gx = tx0 + c - 1;
            float v = 0.f;
            if ((unsigned)gy < (unsigned)Hs && (unsigned)gx < (unsigned)Ws)
                v = fmaf(aa, inc[gy * Ws + gx], cc0);
            xs[r][c] = v;
        }
        #pragma unroll
        for (int i = tid; i < CO_BLK * 9; i += 128)
            ws_s[i / 9][i % 9] = w[((size_t)(co0 + i / 9) * Ci + ci) * 9 + i % 9];
        __syncthreads();

        float xr[PXH + 2][4];
        #pragma unroll
        for (int r = 0; r < PXH + 2; r++)
            #pragma unroll
            for (int c = 0; c < 4; c++)
                xr[r][c] = xs[ly * PXH + r][2 * lx + c];

        #pragma unroll
        for (int u = 0; u < CO_BLK; u++) {
            #pragma unroll
            for (int i = 0; i < 3; i++)
                #pragma unroll
                for (int j = 0; j < 3; j++) {
                    float wv = ws_s[u][i * 3 + j];
                    #pragma unroll
                    for (int r = 0; r < PXH; r++) {
                        acc[u][r][0] = fmaf(xr[i + r][j],     wv, acc[u][r][0]);
                        acc[u][r][1] = fmaf(xr[i + r][j + 1], wv, acc[u][r][1]);
                    }
                }
        }
        __syncthreads();
    }

    int oy = ty0 + ly * PXH, ox = tx0 + 2 * lx;
    #pragma unroll
    for (int u = 0; u < CO_BLK; u++) {
        float bv = BIAS ? bias[co0 + u] : 0.f;
        #pragma unroll
        for (int r = 0; r < PXH; r++) {
            float* op = out + (((size_t)b * Co + co0 + u) * Hs + oy + r) * Ws + ox;
            *(float2*)op = make_float2(acc[u][r][0] + bv, acc[u][r][1] + bv);
        }
    }
}

// ---------------- 1x1 conv + residual, float4 ----------------
__global__ void conv1x1_res4(const float* __restrict__ x, const float* __restrict__ w,
                             const float* __restrict__ bias, float* __restrict__ out,
                             int Cc, int HW4) {
    int p = blockIdx.x * 128 + threadIdx.x;
    int o0 = blockIdx.y * 8;
    int b = blockIdx.z;
    __shared__ float ws[8 * 128];
    for (int i = threadIdx.x; i < 8 * Cc; i += 128)
        ws[i] = w[(o0 + i / Cc) * Cc + i % Cc];
    __syncthreads();
    const float4* xb = (const float4*)x + (size_t)b * Cc * HW4;
    float4 acc[8];
    #pragma unroll
    for (int u = 0; u < 8; u++) acc[u] = make_float4(0.f, 0.f, 0.f, 0.f);
    for (int ci = 0; ci < Cc; ci++) {
        float4 xv = xb[(size_t)ci * HW4 + p];
        #pragma unroll
        for (int u = 0; u < 8; u++) {
            float wv = ws[u * Cc + ci];
            acc[u].x = fmaf(wv, xv.x, acc[u].x);
            acc[u].y = fmaf(wv, xv.y, acc[u].y);
            acc[u].z = fmaf(wv, xv.z, acc[u].z);
            acc[u].w = fmaf(wv, xv.w, acc[u].w);
        }
    }
    float4* ob = (float4*)out + (size_t)b * Cc * HW4;
    #pragma unroll
    for (int u = 0; u < 8; u++) {
        float bv = bias[o0 + u];
        float4 rv = xb[(size_t)(o0 + u) * HW4 + p];
        float4 o;
        o.x = acc[u].x + bv + rv.x;
        o.y = acc[u].y + bv + rv.y;
        o.z = acc[u].z + bv + rv.z;
        o.w = acc[u].w + bv + rv.w;
        ob[(size_t)(o0 + u) * HW4 + p] = o;
    }
}

// ---------------- PAC gaussian kernel ----------------
__global__ void pac_kernel_K(const float* __restrict__ g, float* __restrict__ K,
                             int Cg, int Hg, int Wg) {
    int tiles_x = Wg / 16;
    int tx0 = (blockIdx.x % tiles_x) * 16, ty0 = (blockIdx.x / tiles_x) * 16;
    int b = blockIdx.y;
    int lx = threadIdx.x, ly = threadIdx.y;
    int tid = ly * 16 + lx;
    __shared__ float gs[18][19];
    float acc[9];
    #pragma unroll
    for (int k = 0; k < 9; k++) acc[k] = 0.f;
    const float* gb = g + (size_t)b * Cg * Hg * Wg;
    for (int c = 0; c < Cg; c++) {
        const float* gc = gb + (size_t)c * Hg * Wg;
        #pragma unroll
        for (int i = tid; i < 18 * 18; i += 256) {
            int r = i / 18, cx = i % 18;
            int yy = ty0 + r - 1, xx = tx0 + cx - 1;
            gs[r][cx] = (yy >= 0 && yy < Hg && xx >= 0 && xx < Wg) ? gc[yy * Wg + xx] : 0.f;
        }
        __syncthreads();
        float ctr = gs[ly + 1][lx + 1];
        #pragma unroll
        for (int i = 0; i < 3; i++)
            #pragma unroll
            for (int j = 0; j < 3; j++) {
                float d = gs[ly + i][lx + j] - ctr;
                acc[i * 3 + j] = fmaf(d, d, acc[i * 3 + j]);
            }
        __syncthreads();
    }
    size_t base = ((size_t)b * 9) * Hg * Wg + (size_t)(ty0 + ly) * Wg + tx0 + lx;
    #pragma unroll
    for (int k = 0; k < 9; k++)
        K[base + (size_t)k * Hg * Wg] = __expf(-0.5f * acc[k]);
}

// ---------------- tap GEMM ----------------
__global__ void __launch_bounds__(128) tap_gemm(
        const float* __restrict__ x, const float* __restrict__ w,
        float* __restrict__ M, int Cin, int Co, int HW4,
        const float* __restrict__ na, const float* __restrict__ nc) {
    int p = blockIdx.x * 256 + threadIdx.x;
    int kc0 = blockIdx.y * 8;
    int b = blockIdx.z;
    int k = kc0 / Co, co0 = kc0 % Co;
    __shared__ float ws[8 * 128];
    for (int i = threadIdx.x; i < 8 * Cin; i += 128) {
        int u = i / Cin, ci = i % Cin;
        ws[i] = w[((size_t)ci * Co + co0 + u) * 9 + k];
    }
    __syncthreads();
    const float4* xb = (const float4*)x + (size_t)b * Cin * HW4;
    float4 a0[8], a1[8];
    #pragma unroll
    for (int u = 0; u < 8; u++) { a0[u] = make_float4(0, 0, 0, 0); a1[u] = make_float4(0, 0, 0, 0); }
    for (int ci = 0; ci < Cin; ci++) {
        float4 x0 = xb[(size_t)ci * HW4 + p];
        float4 x1 = xb[(size_t)ci * HW4 + p + 128];
        if (na) {
            float aa = na[b * Cin + ci], cc = nc[b * Cin + ci];
            x0.x = fmaf(aa, x0.x, cc); x0.y = fmaf(aa, x0.y, cc);
            x0.z = fmaf(aa, x0.z, cc); x0.w = fmaf(aa, x0.w, cc);
            x1.x = fmaf(aa, x1.x, cc); x1.y = fmaf(aa, x1.y, cc);
            x1.z = fmaf(aa, x1.z, cc); x1.w = fmaf(aa, x1.w, cc);
        }
        #pragma unroll
        for (int u = 0; u < 8; u++) {
            float wv = ws[u * Cin + ci];
            a0[u].x = fmaf(wv, x0.x, a0[u].x); a0[u].y = fmaf(wv, x0.y, a0[u].y);
            a0[u].z = fmaf(wv, x0.z, a0[u].z); a0[u].w = fmaf(wv, x0.w, a0[u].w);
            a1[u].x = fmaf(wv, x1.x, a1[u].x); a1[u].y = fmaf(wv, x1.y, a1[u].y);
            a1[u].z = fmaf(wv, x1.z, a1[u].z); a1[u].w = fmaf(wv, x1.w, a1[u].w);
        }
    }
    float4* Mb = (float4*)M + (size_t)b * 9 * Co * HW4;
    #pragma unroll
    for (int u = 0; u < 8; u++) {
        Mb[(size_t)(kc0 + u) * HW4 + p] = a0[u];
        Mb[(size_t)(kc0 + u) * HW4 + p + 128] = a1[u];
    }
}

// ---------------- PAC combine ----------------
template<int CO_T>
__global__ void pac_combine(const float* __restrict__ M, const float* __restrict__ K,
                            const float* __restrict__ bias, float* __restrict__ out,
                            int Co, int Hs, int Ws) {
    int Ho = 2 * Hs, Wo = 2 * Ws;
    int px = blockIdx.x * 256 + threadIdx.x;
    int h = px / Wo, w = px % Wo;
    int co0 = blockIdx.y * CO_T;
    int b = blockIdx.z;

    float acc[CO_T];
    #pragma unroll
    for (int u = 0; u < CO_T; u++) acc[u] = bias[co0 + u];

    int nr, ry[2], rk[2];
    if (h & 1) {
        nr = 2; rk[0] = 0; ry[0] = (h - 1) >> 1; rk[1] = 2; ry[1] = (h + 1) >> 1;
        if (ry[1] >= Hs) nr = 1;
    } else { nr = 1; rk[0] = 1; ry[0] = h >> 1; }
    int ncn, cx[2], ck[2];
    if (w & 1) {
        ncn = 2; ck[0] = 0; cx[0] = (w - 1) >> 1; ck[1] = 2; cx[1] = (w + 1) >> 1;
        if (cx[1] >= Ws) ncn = 1;
    } else { ncn = 1; ck[0] = 1; cx[0] = w >> 1; }

    const float* Kb = K + (size_t)b * 9 * Ho * Wo + px;
    const float* Mb = M + (size_t)b * 9 * Co * Hs * Ws;
    int HsWs = Hs * Ws;
    for (int rr = 0; rr < nr; rr++)
        for (int cc = 0; cc < ncn; cc++) {
            int k = rk[rr] * 3 + ck[cc];
            float Kv = __ldg(Kb + (size_t)k * Ho * Wo);
            const float* Mp = Mb + ((size_t)k * Co + co0) * HsWs + ry[rr] * Ws + cx[cc];
            #pragma unroll
            for (int u = 0; u < CO_T; u++)
                acc[u] = fmaf(Kv, __ldg(Mp + (size_t)u * HsWs), acc[u]);
        }
    #pragma unroll
    for (int u = 0; u < CO_T; u++)
        out[(((size_t)b * Co + co0 + u) * Ho + h) * Wo + w] = acc[u];
}

// ---------------- driver ----------------
extern "C" void kernel_launch(void* const* d_in, const int* in_sizes, int n_in,
                              void* d_out, int out_size) {
    const float* x      = (const float*)d_in[0];
    const float* ef2    = (const float*)d_in[1];
    const float* ef1    = (const float*)d_in[2];
    const float* W_down = (const float*)d_in[3];
    const float* b_down = (const float*)d_in[4];
    const float* W_mid  = (const float*)d_in[5];
    const float* b_mid  = (const float*)d_in[6];
    const float* W_adj2 = (const float*)d_in[7];
    const float* b_adj2 = (const float*)d_in[8];
    const float* W_adj1 = (const float*)d_in[9];
    const float* b_adj1 = (const float*)d_in[10];
    const float* W16    = (const float*)d_in[11];
    const float* b16    = (const float*)d_in[12];
    const float* W20    = (const float*)d_in[13];
    const float* b20    = (const float*)d_in[14];
    const float* W24    = (const float*)d_in[15];
    const float* b24    = (const float*)d_in[16];
    float* out = (float*)d_out;

    float *t1, *t2, *g2, *K1, *M1, *y1, *g1, *K2, *M2, *y2, *na, *nc;
    cudaGetSymbolAddress((void**)&t1, g_t1);
    cudaGetSymbolAddress((void**)&t2, g_t2);
    cudaGetSymbolAddress((void**)&g2, g_g2);
    cudaGetSymbolAddress((void**)&K1, g_K1);
    cudaGetSymbolAddress((void**)&M1, g_M1);
    cudaGetSymbolAddress((void**)&y1, g_y1);
    cudaGetSymbolAddress((void**)&g1, g_g1);
    cudaGetSymbolAddress((void**)&K2, g_K2);
    cudaGetSymbolAddress((void**)&M2, g_M2);
    cudaGetSymbolAddress((void**)&y2, g_y2);
    cudaGetSymbolAddress((void**)&na, g_na);
    cudaGetSymbolAddress((void**)&nc, g_nc);

    dim3 cblk(16, 8);
    dim3 blk16(16, 16);

    // 1) inorm(x) coefficients
    stats_coef<0><<<512, 256>>>(x, 64 * 64, na, nc);

    // 2) conv_down 256->128 @64x64 (tf32 mma, norm fused, bias included)
    conv3x3_mma<<<dim3(64, 2, 2), 256>>>(x, W_down, b_down, t1, 256, 128, 64, 64, na, nc);

    // 3) 1x1 + residual
    conv1x1_res4<<<dim3(8, 16, 2), 128>>>(t1, W_mid, b_mid, t2, 128, 1024);

    // 4) g2 = adjust_ef_lv2: 64->128 @128x128 (tf32 mma)
    conv3x3_mma<<<dim3(256, 2, 2), 256>>>(ef2, W_adj2, b_adj2, g2, 64, 128, 128, 128,
                                          (const float*)0, (const float*)0);

    // 5) PAC kernel 1
    pac_kernel_K<<<dim3(64, 2), blk16>>>(g2, K1, 128, 128, 128);

    // 6) pacT1 = tap GEMM + combine
    tap_gemm<<<dim3(4, 72, 2), 128>>>(t2, W16, M1, 128, 64, 1024,
                                      (const float*)0, (const float*)0);
    pac_combine<8><<<dim3(64, 8, 2), 256>>>(M1, K1, b16, y1, 64, 64, 64);

    // 7) dinorm coefs for y1
    stats_coef<1><<<128, 256>>>(y1, 128 * 128, na, nc);

    // 8) g1 = adjust_ef_lv1: 32->64 @256x256 (tf32 mma)
    conv3x3_mma<<<dim3(1024, 1, 2), 256>>>(ef1, W_adj1, b_adj1, g1, 32, 64, 256, 256,
                                           (const float*)0, (const float*)0);

    // 9) PAC kernel 2
    pac_kernel_K<<<dim3(256, 2), blk16>>>(g1, K2, 64, 256, 256);

    // 10) pacT2 = tap GEMM (y1 affine fused) + combine
    tap_gemm<<<dim3(16, 36, 2), 128>>>(y1, W20, M2, 64, 32, 4096, na, nc);
    pac_combine<8><<<dim3(256, 4, 2), 256>>>(M2, K2, b20, y2, 32, 128, 128);

    // 11) dinorm coefs for y2
    stats_coef<1><<<64, 256>>>(y2, 256 * 256, na, nc);

    // 12) final conv 32->3 @256x256 (y2 affine fused, scalar)
    conv3x3_v2<3, 2, true><<<dim3(128, 1, 2), cblk>>>(y2, W24, b24, out,
                                                      32, 3, 256, 256, na, nc);
}

// round 10
// speedup vs baseline: 1.5493x; 1.5493x over previous
#include <cuda_runtime.h>
#include <math.h>
#include <stdint.h>

#define EPS 1e-5f

__device__ __forceinline__ float to_tf32(float x) {
    uint32_t r;
    asm("cvt.rna.tf32.f32 %0, %1;" : "=r"(r) : "f"(x));
    return __uint_as_float(r);
}

// ---------------- static scratch ----------------
__device__ float g_t1[2*128*64*64];
__device__ float g_part[4*128*64*64];
__device__ float g_t2[2*128*64*64];
__device__ float g_g2[2*128*128*128];
__device__ float g_K1[2*9*128*128];
__device__ float g_M1[2*9*64*64*64];
__device__ float g_y1[2*64*128*128];
__device__ float g_g1[2*64*256*256];
__device__ float g_K2[2*9*256*256];
__device__ float g_M2[2*9*32*128*128];
__device__ float g_y2[2*32*256*256];
__device__ float g_na[1024];
__device__ float g_nc[1024];

// ---------------- instance stats + fused coefficient ----------------
template<int DMODE>
__global__ void stats_coef(const float* __restrict__ x, int HW,
                           float* __restrict__ na, float* __restrict__ nc) {
    int bc = blockIdx.x;
    const float* p = x + (size_t)bc * HW;
    float s = 0.f, ss = 0.f;
    for (int i = threadIdx.x; i < HW; i += blockDim.x) {
        float v = p[i]; s += v; ss += v * v;
    }
    __shared__ float sh0[32], sh1[32];
    for (int o = 16; o; o >>= 1) {
        s  += __shfl_down_sync(0xffffffffu, s, o);
        ss += __shfl_down_sync(0xffffffffu, ss, o);
    }
    int wid = threadIdx.x >> 5, lid = threadIdx.x & 31;
    if (lid == 0) { sh0[wid] = s; sh1[wid] = ss; }
    __syncthreads();
    if (wid == 0) {
        int nw = blockDim.x >> 5;
        s  = (lid < nw) ? sh0[lid] : 0.f;
        ss = (lid < nw) ? sh1[lid] : 0.f;
        for (int o = 16; o; o >>= 1) {
            s  += __shfl_down_sync(0xffffffffu, s, o);
            ss += __shfl_down_sync(0xffffffffu, ss, o);
        }
        if (lid == 0) {
            float m = s / (float)HW;
            float v = ss / (float)HW - m * m;
            if (DMODE == 0) {
                float r = rsqrtf(v + EPS);
                na[bc] = r; nc[bc] = -m * r;
            } else {
                float r1 = rsqrtf(v + EPS);
                float a1 = 1.f + r1, c1 = -m * r1;
                float m2 = a1 * m + c1;
                float v2 = a1 * a1 * v;
                float r2 = rsqrtf(v2 + EPS);
                na[bc] = a1 * (1.f + r2);
                nc[bc] = c1 * (1.f + r2) - m2 * r2;
            }
        }
    }
}

// ---------------- tf32 mma implicit-GEMM 3x3 conv v2 ----------------
// 256 thr = 8 warps; block tile 64co x (8 rows x 32 cols); warp tile 32co x 64px.
// grid ((Ws/32)*(Hs/8), Co/64, B*CI_SPLIT). w layout (Co,Ci,3,3).
template<int CI_SPLIT, bool BIAS>
__global__ void __launch_bounds__(256) conv3x3_mma2(
        const float* __restrict__ in, const float* __restrict__ w,
        const float* __restrict__ bias, float* __restrict__ out,
        int Ci, int Co, int Hs, int Ws,
        const float* __restrict__ na, const float* __restrict__ nc) {
    const int KC = 8;
    __shared__ float Xs[KC][10][36];    // k-stride 360 ≡ 8 (mod 32) -> conflict-free
    __shared__ float Wss[9][KC][72];    // k-stride 72  ≡ 8 (mod 32) -> conflict-free

    int tpr = Ws >> 5;
    int ty = blockIdx.x / tpr, tx = blockIdx.x - ty * tpr;
    int y0 = ty << 3, x0 = tx << 5;
    int co0 = blockIdx.y << 6;
    int zz = blockIdx.z;
    int b = zz / CI_SPLIT, gsp = zz % CI_SPLIT;
    int ciN = Ci / CI_SPLIT, ci0 = gsp * ciN;
    int tid = threadIdx.x;
    int lane = tid & 31, wid = tid >> 5;
    int cog = wid & 1;          // 0,1 -> co halves of 32
    int pxg = wid >> 1;         // 0..3 -> 2-row groups
    int tig = lane & 3, grp = lane >> 2;
    int HsWs = Hs * Ws;

    float acc[2][8][4] = {};
    const float* inb = in + ((size_t)b * Ci + ci0) * HsWs;

    for (int cc = 0; cc < ciN; cc += KC) {
        // stage X: KC channels x 10 rows x 34 cols (halo, zero pad, affine fused)
        for (int e = tid; e < KC * 340; e += 256) {
            int k = e / 340, rem = e - k * 340;
            int r = rem / 34, c = rem - r * 34;
            int yy = y0 + r - 1, xx = x0 + c - 1;
            float v = 0.f;
            if ((unsigned)yy < (unsigned)Hs && (unsigned)xx < (unsigned)Ws) {
                v = inb[(size_t)(cc + k) * HsWs + yy * Ws + xx];
                if (na) v = fmaf(na[b * Ci + ci0 + cc + k], v, nc[b * Ci + ci0 + cc + k]);
            }
            Xs[k][r][c] = to_tf32(v);
        }
        // stage W: Wss[tap][k][co]
        for (int e = tid; e < 9 * KC * 64; e += 256) {
            int tap = e / (KC * 64), rem = e - tap * KC * 64;
            int k = rem >> 6, co = rem & 63;
            Wss[tap][k][co] = to_tf32(w[((size_t)(co0 + co) * Ci + ci0 + cc + k) * 9 + tap]);
        }
        __syncthreads();

        #pragma unroll
        for (int dy = 0; dy < 3; dy++)
            #pragma unroll
            for (int dx = 0; dx < 3; dx++) {
                int tap = dy * 3 + dx;
                uint32_t a[2][4];
                #pragma unroll
                for (int mt = 0; mt < 2; mt++) {
                    int cb = cog * 32 + mt * 16;
                    a[mt][0] = __float_as_uint(Wss[tap][tig][cb + grp]);
                    a[mt][1] = __float_as_uint(Wss[tap][tig][cb + grp + 8]);
                    a[mt][2] = __float_as_uint(Wss[tap][tig + 4][cb + grp]);
                    a[mt][3] = __float_as_uint(Wss[tap][tig + 4][cb + grp + 8]);
                }
                #pragma unroll
                for (int nt = 0; nt < 8; nt++) {
                    int r = pxg * 2 + (nt >> 2) + dy;
                    int c = (nt & 3) * 8 + grp + dx;
                    uint32_t b0 = __float_as_uint(Xs[tig][r][c]);
                    uint32_t b1 = __float_as_uint(Xs[tig + 4][r][c]);
                    #pragma unroll
                    for (int mt = 0; mt < 2; mt++)
                        asm volatile(
                            "mma.sync.aligned.m16n8k8.row.col.f32.tf32.tf32.f32 "
                            "{%0,%1,%2,%3}, {%4,%5,%6,%7}, {%8,%9}, {%0,%1,%2,%3};"
                            : "+f"(acc[mt][nt][0]), "+f"(acc[mt][nt][1]),
                              "+f"(acc[mt][nt][2]), "+f"(acc[mt][nt][3])
                            : "r"(a[mt][0]), "r"(a[mt][1]), "r"(a[mt][2]), "r"(a[mt][3]),
                              "r"(b0), "r"(b1));
                }
            }
        __syncthreads();
    }

    #pragma unroll
    for (int mt = 0; mt < 2; mt++) {
        int coA = co0 + cog * 32 + mt * 16 + grp;
        int coB = coA + 8;
        float bvA = BIAS ? bias[coA] : 0.f;
        float bvB = BIAS ? bias[coB] : 0.f;
        #pragma unroll
        for (int nt = 0; nt < 8; nt++) {
            int y = y0 + pxg * 2 + (nt >> 2);
            int x = x0 + (nt & 3) * 8 + tig * 2;
            float* pA = out + (((size_t)zz * Co + coA) * Hs + y) * Ws + x;
            float* pB = out + (((size_t)zz * Co + coB) * Hs + y) * Ws + x;
            *(float2*)pA = make_float2(acc[mt][nt][0] + bvA, acc[mt][nt][1] + bvA);
            *(float2*)pB = make_float2(acc[mt][nt][2] + bvB, acc[mt][nt][3] + bvB);
        }
    }
}

// reduce 2 ci-split partials + bias
__global__ void reduce2_bias(const float* __restrict__ p, const float* __restrict__ bias,
                             float* __restrict__ out, int Co, int HW, int N) {
    int i = blockIdx.x * 256 + threadIdx.x;
    if (i >= N) return;
    int b = i / (Co * HW);
    int rem = i - b * Co * HW;
    int co = rem / HW;
    out[i] = p[(size_t)(2 * b) * Co * HW + rem] + p[(size_t)(2 * b + 1) * Co * HW + rem] + bias[co];
}

// ---------------- scalar 3x3 conv (final 3-channel layer only) ----------------
template<int CO_BLK, int PXH, bool BIAS>
__global__ void __launch_bounds__(128) conv3x3_v2(
        const float* __restrict__ in, const float* __restrict__ w,
        const float* __restrict__ bias, float* __restrict__ out,
        int Ci, int Co, int Hs, int Ws,
        const float* __restrict__ na, const float* __restrict__ nc) {
    const int TW = 32, TH = 8 * PXH;
    int tiles_x = Ws / TW;
    int tx0 = (blockIdx.x % tiles_x) * TW;
    int ty0 = (blockIdx.x / tiles_x) * TH;
    int co0 = blockIdx.y * CO_BLK;
    int b = blockIdx.z;
    int lx = threadIdx.x, ly = threadIdx.y;
    int tid = ly * 16 + lx;

    __shared__ float xs[TH + 2][TW + 4];
    __shared__ float ws_s[CO_BLK][9];

    float acc[CO_BLK][PXH][2];
    #pragma unroll
    for (int u = 0; u < CO_BLK; u++)
        #pragma unroll
        for (int r = 0; r < PXH; r++) { acc[u][r][0] = 0.f; acc[u][r][1] = 0.f; }

    const float* inb = in + (size_t)b * Ci * Hs * Ws;
    for (int ci = 0; ci < Ci; ci++) {
        const float* inc = inb + (size_t)ci * Hs * Ws;
        float aa = 1.f, cc0 = 0.f;
        if (na) { aa = na[b * Ci + ci]; cc0 = nc[b * Ci + ci]; }
        #pragma unroll 4
        for (int i = tid; i < (TH + 2) * (TW + 2); i += 128) {
            int r = i / (TW + 2), c = i % (TW + 2);
            int gy = ty0 + r - 1, gx = tx0 + c - 1;
            float v = 0.f;
            if ((unsigned)gy < (unsigned)Hs && (unsigned)gx < (unsigned)Ws)
                v = fmaf(aa, inc[gy * Ws + gx], cc0);
            xs[r][c] = v;
        }
        #pragma unroll
        for (int i = tid; i < CO_BLK * 9; i += 128)
            ws_s[i / 9][i % 9] = w[((size_t)(co0 + i / 9) * Ci + ci) * 9 + i % 9];
        __syncthreads();

        float xr[PXH + 2][4];
        #pragma unroll
        for (int r = 0; r < PXH + 2; r++)
            #pragma unroll
            for (int c = 0; c < 4; c++)
                xr[r][c] = xs[ly * PXH + r][2 * lx + c];

        #pragma unroll
        for (int u = 0; u < CO_BLK; u++) {
            #pragma unroll
            for (int i = 0; i < 3; i++)
                #pragma unroll
                for (int j = 0; j < 3; j++) {
                    float wv = ws_s[u][i * 3 + j];
                    #pragma unroll
                    for (int r = 0; r < PXH; r++) {
                        acc[u][r][0] = fmaf(xr[i + r][j],     wv, acc[u][r][0]);
                        acc[u][r][1] = fmaf(xr[i + r][j + 1], wv, acc[u][r][1]);
                    }
                }
        }
        __syncthreads();
    }

    int oy = ty0 + ly * PXH, ox = tx0 + 2 * lx;
    #pragma unroll
    for (int u = 0; u < CO_BLK; u++) {
        float bv = BIAS ? bias[co0 + u] : 0.f;
        #pragma unroll
        for (int r = 0; r < PXH; r++) {
            float* op = out + (((size_t)b * Co + co0 + u) * Hs + oy + r) * Ws + ox;
            *(float2*)op = make_float2(acc[u][r][0] + bv, acc[u][r][1] + bv);
        }
    }
}

// ---------------- 1x1 conv + residual, float4 ----------------
__global__ void conv1x1_res4(const float* __restrict__ x, const float* __restrict__ w,
                             const float* __restrict__ bias, float* __restrict__ out,
                             int Cc, int HW4) {
    int p = blockIdx.x * 128 + threadIdx.x;
    int o0 = blockIdx.y * 8;
    int b = blockIdx.z;
    __shared__ float ws[8 * 128];
    for (int i = threadIdx.x; i < 8 * Cc; i += 128)
        ws[i] = w[(o0 + i / Cc) * Cc + i % Cc];
    __syncthreads();
    const float4* xb = (const float4*)x + (size_t)b * Cc * HW4;
    float4 acc[8];
    #pragma unroll
    for (int u = 0; u < 8; u++) acc[u] = make_float4(0.f, 0.f, 0.f, 0.f);
    for (int ci = 0; ci < Cc; ci++) {
        float4 xv = xb[(size_t)ci * HW4 + p];
        #pragma unroll
        for (int u = 0; u < 8; u++) {
            float wv = ws[u * Cc + ci];
            acc[u].x = fmaf(wv, xv.x, acc[u].x);
            acc[u].y = fmaf(wv, xv.y, acc[u].y);
            acc[u].z = fmaf(wv, xv.z, acc[u].z);
            acc[u].w = fmaf(wv, xv.w, acc[u].w);
        }
    }
    float4* ob = (float4*)out + (size_t)b * Cc * HW4;
    #pragma unroll
    for (int u = 0; u < 8; u++) {
        float bv = bias[o0 + u];
        float4 rv = xb[(size_t)(o0 + u) * HW4 + p];
        float4 o;
        o.x = acc[u].x + bv + rv.x;
        o.y = acc[u].y + bv + rv.y;
        o.z = acc[u].z + bv + rv.z;
        o.w = acc[u].w + bv + rv.w;
        ob[(size_t)(o0 + u) * HW4 + p] = o;
    }
}

// ---------------- PAC gaussian kernel ----------------
__global__ void pac_kernel_K(const float* __restrict__ g, float* __restrict__ K,
                             int Cg, int Hg, int Wg) {
    int tiles_x = Wg / 16;
    int tx0 = (blockIdx.x % tiles_x) * 16, ty0 = (blockIdx.x / tiles_x) * 16;
    int b = blockIdx.y;
    int lx = threadIdx.x, ly = threadIdx.y;
    int tid = ly * 16 + lx;
    __shared__ float gs[18][19];
    float acc[9];
    #pragma unroll
    for (int k = 0; k < 9; k++) acc[k] = 0.f;
    const float* gb = g + (size_t)b * Cg * Hg * Wg;
    for (int c = 0; c < Cg; c++) {
        const float* gc = gb + (size_t)c * Hg * Wg;
        #pragma unroll
        for (int i = tid; i < 18 * 18; i += 256) {
            int r = i / 18, cx = i % 18;
            int yy = ty0 + r - 1, xx = tx0 + cx - 1;
            gs[r][cx] = (yy >= 0 && yy < Hg && xx >= 0 && xx < Wg) ? gc[yy * Wg + xx] : 0.f;
        }
        __syncthreads();
        float ctr = gs[ly + 1][lx + 1];
        #pragma unroll
        for (int i = 0; i < 3; i++)
            #pragma unroll
            for (int j = 0; j < 3; j++) {
                float d = gs[ly + i][lx + j] - ctr;
                acc[i * 3 + j] = fmaf(d, d, acc[i * 3 + j]);
            }
        __syncthreads();
    }
    size_t base = ((size_t)b * 9) * Hg * Wg + (size_t)(ty0 + ly) * Wg + tx0 + lx;
    #pragma unroll
    for (int k = 0; k < 9; k++)
        K[base + (size_t)k * Hg * Wg] = __expf(-0.5f * acc[k]);
}

// ---------------- tap GEMM ----------------
__global__ void __launch_bounds__(128) tap_gemm(
        const float* __restrict__ x, const float* __restrict__ w,
        float* __restrict__ M, int Cin, int Co, int HW4,
        const float* __restrict__ na, const float* __restrict__ nc) {
    int p = blockIdx.x * 256 + threadIdx.x;
    int kc0 = blockIdx.y * 8;
    int b = blockIdx.z;
    int k = kc0 / Co, co0 = kc0 % Co;
    __shared__ float ws[8 * 128];
    for (int i = threadIdx.x; i < 8 * Cin; i += 128) {
        int u = i / Cin, ci = i % Cin;
        ws[i] = w[((size_t)ci * Co + co0 + u) * 9 + k];
    }
    __syncthreads();
    const float4* xb = (const float4*)x + (size_t)b * Cin * HW4;
    float4 a0[8], a1[8];
    #pragma unroll
    for (int u = 0; u < 8; u++) { a0[u] = make_float4(0, 0, 0, 0); a1[u] = make_float4(0, 0, 0, 0); }
    for (int ci = 0; ci < Cin; ci++) {
        float4 x0 = xb[(size_t)ci * HW4 + p];
        float4 x1 = xb[(size_t)ci * HW4 + p + 128];
        if (na) {
            float aa = na[b * Cin + ci], cc = nc[b * Cin + ci];
            x0.x = fmaf(aa, x0.x, cc); x0.y = fmaf(aa, x0.y, cc);
            x0.z = fmaf(aa, x0.z, cc); x0.w = fmaf(aa, x0.w, cc);
            x1.x = fmaf(aa, x1.x, cc); x1.y = fmaf(aa, x1.y, cc);
            x1.z = fmaf(aa, x1.z, cc); x1.w = fmaf(aa, x1.w, cc);
        }
        #pragma unroll
        for (int u = 0; u < 8; u++) {
            float wv = ws[u * Cin + ci];
            a0[u].x = fmaf(wv, x0.x, a0[u].x); a0[u].y = fmaf(wv, x0.y, a0[u].y);
            a0[u].z = fmaf(wv, x0.z, a0[u].z); a0[u].w = fmaf(wv, x0.w, a0[u].w);
            a1[u].x = fmaf(wv, x1.x, a1[u].x); a1[u].y = fmaf(wv, x1.y, a1[u].y);
            a1[u].z = fmaf(wv, x1.z, a1[u].z); a1[u].w = fmaf(wv, x1.w, a1[u].w);
        }
    }
    float4* Mb = (float4*)M + (size_t)b * 9 * Co * HW4;
    #pragma unroll
    for (int u = 0; u < 8; u++) {
        Mb[(size_t)(kc0 + u) * HW4 + p] = a0[u];
        Mb[(size_t)(kc0 + u) * HW4 + p + 128] = a1[u];
    }
}

// ---------------- PAC combine ----------------
template<int CO_T>
__global__ void pac_combine(const float* __restrict__ M, const float* __restrict__ K,
                            const float* __restrict__ bias, float* __restrict__ out,
                            int Co, int Hs, int Ws) {
    int Ho = 2 * Hs, Wo = 2 * Ws;
    int px = blockIdx.x * 256 + threadIdx.x;
    int h = px / Wo, w = px % Wo;
    int co0 = blockIdx.y * CO_T;
    int b = blockIdx.z;

    float acc[CO_T];
    #pragma unroll
    for (int u = 0; u < CO_T; u++) acc[u] = bias[co0 + u];

    int nr, ry[2], rk[2];
    if (h & 1) {
        nr = 2; rk[0] = 0; ry[0] = (h - 1) >> 1; rk[1] = 2; ry[1] = (h + 1) >> 1;
        if (ry[1] >= Hs) nr = 1;
    } else { nr = 1; rk[0] = 1; ry[0] = h >> 1; }
    int ncn, cx[2], ck[2];
    if (w & 1) {
        ncn = 2; ck[0] = 0; cx[0] = (w - 1) >> 1; ck[1] = 2; cx[1] = (w + 1) >> 1;
        if (cx[1] >= Ws) ncn = 1;
    } else { ncn = 1; ck[0] = 1; cx[0] = w >> 1; }

    const float* Kb = K + (size_t)b * 9 * Ho * Wo + px;
    const float* Mb = M + (size_t)b * 9 * Co * Hs * Ws;
    int HsWs = Hs * Ws;
    for (int rr = 0; rr < nr; rr++)
        for (int cc = 0; cc < ncn; cc++) {
            int k = rk[rr] * 3 + ck[cc];
            float Kv = __ldg(Kb + (size_t)k * Ho * Wo);
            const float* Mp = Mb + ((size_t)k * Co + co0) * HsWs + ry[rr] * Ws + cx[cc];
            #pragma unroll
            for (int u = 0; u < CO_T; u++)
                acc[u] = fmaf(Kv, __ldg(Mp + (size_t)u * HsWs), acc[u]);
        }
    #pragma unroll
    for (int u = 0; u < CO_T; u++)
        out[(((size_t)b * Co + co0 + u) * Ho + h) * Wo + w] = acc[u];
}

// ---------------- driver ----------------
extern "C" void kernel_launch(void* const* d_in, const int* in_sizes, int n_in,
                              void* d_out, int out_size) {
    const float* x      = (const float*)d_in[0];
    const float* ef2    = (const float*)d_in[1];
    const float* ef1    = (const float*)d_in[2];
    const float* W_down = (const float*)d_in[3];
    const float* b_down = (const float*)d_in[4];
    const float* W_mid  = (const float*)d_in[5];
    const float* b_mid  = (const float*)d_in[6];
    const float* W_adj2 = (const float*)d_in[7];
    const float* b_adj2 = (const float*)d_in[8];
    const float* W_adj1 = (const float*)d_in[9];
    const float* b_adj1 = (const float*)d_in[10];
    const float* W16    = (const float*)d_in[11];
    const float* b16    = (const float*)d_in[12];
    const float* W20    = (const float*)d_in[13];
    const float* b20    = (const float*)d_in[14];
    const float* W24    = (const float*)d_in[15];
    const float* b24    = (const float*)d_in[16];
    float* out = (float*)d_out;

    float *t1, *part, *t2, *g2, *K1, *M1, *y1, *g1, *K2, *M2, *y2, *na, *nc;
    cudaGetSymbolAddress((void**)&t1, g_t1);
    cudaGetSymbolAddress((void**)&part, g_part);
    cudaGetSymbolAddress((void**)&t2, g_t2);
    cudaGetSymbolAddress((void**)&g2, g_g2);
    cudaGetSymbolAddress((void**)&K1, g_K1);
    cudaGetSymbolAddress((void**)&M1, g_M1);
    cudaGetSymbolAddress((void**)&y1, g_y1);
    cudaGetSymbolAddress((void**)&g1, g_g1);
    cudaGetSymbolAddress((void**)&K2, g_K2);
    cudaGetSymbolAddress((void**)&M2, g_M2);
    cudaGetSymbolAddress((void**)&y2, g_y2);
    cudaGetSymbolAddress((void**)&na, g_na);
    cudaGetSymbolAddress((void**)&nc, g_nc);

    dim3 cblk(16, 8);
    dim3 blk16(16, 16);

    // 1) inorm(x) coefficients
    stats_coef<0><<<512, 256>>>(x, 64 * 64, na, nc);

    // 2) conv_down 256->128 @64x64 (tf32 mma, norm fused, ci-split 2), then reduce+bias
    conv3x3_mma2<2, false><<<dim3(16, 2, 4), 256>>>(x, W_down, b_down, part,
                                                    256, 128, 64, 64, na, nc);
    reduce2_bias<<<4096, 256>>>(part, b_down, t1, 128, 64 * 64, 2 * 128 * 64 * 64);

    // 3) 1x1 + residual
    conv1x1_res4<<<dim3(8, 16, 2), 128>>>(t1, W_mid, b_mid, t2, 128, 1024);

    // 4) g2 = adjust_ef_lv2: 64->128 @128x128 (tf32 mma)
    conv3x3_mma2<1, true><<<dim3(64, 2, 2), 256>>>(ef2, W_adj2, b_adj2, g2,
                                                   64, 128, 128, 128,
                                                   (const float*)0, (const float*)0);

    // 5) PAC kernel 1
    pac_kernel_K<<<dim3(64, 2), blk16>>>(g2, K1, 128, 128, 128);

    // 6) pacT1 = tap GEMM + combine
    tap_gemm<<<dim3(4, 72, 2), 128>>>(t2, W16, M1, 128, 64, 1024,
                                      (const float*)0, (const float*)0);
    pac_combine<8><<<dim3(64, 8, 2), 256>>>(M1, K1, b16, y1, 64, 64, 64);

    // 7) dinorm coefs for y1
    stats_coef<1><<<128, 256>>>(y1, 128 * 128, na, nc);

    // 8) g1 = adjust_ef_lv1: 32->64 @256x256 (tf32 mma)
    conv3x3_mma2<1, true><<<dim3(256, 1, 2), 256>>>(ef1, W_adj1, b_adj1, g1,
                                                    32, 64, 256, 256,
                                                    (const float*)0, (const float*)0);

    // 9) PAC kernel 2
    pac_kernel_K<<<dim3(256, 2), blk16>>>(g1, K2, 64, 256, 256);

    // 10) pacT2 = tap GEMM (y1 affine fused) + combine
    tap_gemm<<<dim3(16, 36, 2), 128>>>(y1, W20, M2, 64, 32, 4096, na, nc);
    pac_combine<8><<<dim3(256, 4, 2), 256>>>(M2, K2, b20, y2, 32, 128, 128);

    // 11) dinorm coefs for y2
    stats_coef<1><<<64, 256>>>(y2, 256 * 256, na, nc);

    // 12) final conv 32->3 @256x256 (y2 affine fused, scalar)
    conv3x3_v2<3, 2, true><<<dim3(128, 1, 2), cblk>>>(y2, W24, b24, out,
                                                      32, 3, 256, 256, na, nc);
}

// round 14
// speedup vs baseline: 1.6691x; 1.0773x over previous
#include <cuda_runtime.h>
#include <math.h>
#include <stdint.h>

#define EPS 1e-5f

__device__ __forceinline__ float to_tf32(float x) {
    uint32_t r;
    asm("cvt.rna.tf32.f32 %0, %1;" : "=r"(r) : "f"(x));
    return __uint_as_float(r);
}

// ---------------- static scratch ----------------
__device__ float g_t1[2*128*64*64];
__device__ float g_part[4*128*64*64];
__device__ float g_t2[2*128*64*64];
__device__ float g_g2[2*128*128*128];
__device__ float g_K1[2*9*128*128];
__device__ float g_Kp[2*4*9*128*128];
__device__ float g_M1[2*9*64*64*64];
__device__ float g_y1[2*64*128*128];
__device__ float g_g1[2*64*256*256];
__device__ float g_K2[2*9*256*256];
__device__ float g_M2[2*9*32*128*128];
__device__ float g_y2[2*32*256*256];
__device__ float g_na[1024];
__device__ float g_nc[1024];

// ---------------- instance stats + fused coefficient ----------------
template<int DMODE>
__global__ void stats_coef(const float* __restrict__ x, int HW,
                           float* __restrict__ na, float* __restrict__ nc) {
    int bc = blockIdx.x;
    const float* p = x + (size_t)bc * HW;
    float s = 0.f, ss = 0.f;
    for (int i = threadIdx.x; i < HW; i += blockDim.x) {
        float v = p[i]; s += v; ss += v * v;
    }
    __shared__ float sh0[32], sh1[32];
    for (int o = 16; o; o >>= 1) {
        s  += __shfl_down_sync(0xffffffffu, s, o);
        ss += __shfl_down_sync(0xffffffffu, ss, o);
    }
    int wid = threadIdx.x >> 5, lid = threadIdx.x & 31;
    if (lid == 0) { sh0[wid] = s; sh1[wid] = ss; }
    __syncthreads();
    if (wid == 0) {
        int nw = blockDim.x >> 5;
        s  = (lid < nw) ? sh0[lid] : 0.f;
        ss = (lid < nw) ? sh1[lid] : 0.f;
        for (int o = 16; o; o >>= 1) {
            s  += __shfl_down_sync(0xffffffffu, s, o);
            ss += __shfl_down_sync(0xffffffffu, ss, o);
        }
        if (lid == 0) {
            float m = s / (float)HW;
            float v = ss / (float)HW - m * m;
            if (DMODE == 0) {
                float r = rsqrtf(v + EPS);
                na[bc] = r; nc[bc] = -m * r;
            } else {
                float r1 = rsqrtf(v + EPS);
                float a1 = 1.f + r1, c1 = -m * r1;
                float m2 = a1 * m + c1;
                float v2 = a1 * a1 * v;
                float r2 = rsqrtf(v2 + EPS);
                na[bc] = a1 * (1.f + r2);
                nc[bc] = c1 * (1.f + r2) - m2 * r2;
            }
        }
    }
}

// ---------------- tf32 mma implicit-GEMM 3x3 conv ----------------
// 256 thr = 8 warps; block tile 64co x (8 rows x 32 cols); warp tile 32co x 64px.
template<int CI_SPLIT, bool BIAS>
__global__ void __launch_bounds__(256) conv3x3_mma2(
        const float* __restrict__ in, const float* __restrict__ w,
        const float* __restrict__ bias, float* __restrict__ out,
        int Ci, int Co, int Hs, int Ws,
        const float* __restrict__ na, const float* __restrict__ nc) {
    const int KC = 8;
    __shared__ float Xs[KC][10][36];
    __shared__ float Wss[9][KC][72];

    int tpr = Ws >> 5;
    int ty = blockIdx.x / tpr, tx = blockIdx.x - ty * tpr;
    int y0 = ty << 3, x0 = tx << 5;
    int co0 = blockIdx.y << 6;
    int zz = blockIdx.z;
    int b = zz / CI_SPLIT, gsp = zz % CI_SPLIT;
    int ciN = Ci / CI_SPLIT, ci0 = gsp * ciN;
    int tid = threadIdx.x;
    int lane = tid & 31, wid = tid >> 5;
    int cog = wid & 1;
    int pxg = wid >> 1;
    int tig = lane & 3, grp = lane >> 2;
    int HsWs = Hs * Ws;

    float acc[2][8][4] = {};
    const float* inb = in + ((size_t)b * Ci + ci0) * HsWs;

    for (int cc = 0; cc < ciN; cc += KC) {
        for (int e = tid; e < KC * 340; e += 256) {
            int k = e / 340, rem = e - k * 340;
            int r = rem / 34, c = rem - r * 34;
            int yy = y0 + r - 1, xx = x0 + c - 1;
            float v = 0.f;
            if ((unsigned)yy < (unsigned)Hs && (unsigned)xx < (unsigned)Ws) {
                v = inb[(size_t)(cc + k) * HsWs + yy * Ws + xx];
                if (na) v = fmaf(na[b * Ci + ci0 + cc + k], v, nc[b * Ci + ci0 + cc + k]);
            }
            Xs[k][r][c] = to_tf32(v);
        }
        for (int e = tid; e < 9 * KC * 64; e += 256) {
            int tap = e / (KC * 64), rem = e - tap * KC * 64;
            int k = rem >> 6, co = rem & 63;
            Wss[tap][k][co] = to_tf32(w[((size_t)(co0 + co) * Ci + ci0 + cc + k) * 9 + tap]);
        }
        __syncthreads();

        #pragma unroll
        for (int dy = 0; dy < 3; dy++)
            #pragma unroll
            for (int dx = 0; dx < 3; dx++) {
                int tap = dy * 3 + dx;
                uint32_t a[2][4];
                #pragma unroll
                for (int mt = 0; mt < 2; mt++) {
                    int cb = cog * 32 + mt * 16;
                    a[mt][0] = __float_as_uint(Wss[tap][tig][cb + grp]);
                    a[mt][1] = __float_as_uint(Wss[tap][tig][cb + grp + 8]);
                    a[mt][2] = __float_as_uint(Wss[tap][tig + 4][cb + grp]);
                    a[mt][3] = __float_as_uint(Wss[tap][tig + 4][cb + grp + 8]);
                }
                #pragma unroll
                for (int nt = 0; nt < 8; nt++) {
                    int r = pxg * 2 + (nt >> 2) + dy;
                    int c = (nt & 3) * 8 + grp + dx;
                    uint32_t b0 = __float_as_uint(Xs[tig][r][c]);
                    uint32_t b1 = __float_as_uint(Xs[tig + 4][r][c]);
                    #pragma unroll
                    for (int mt = 0; mt < 2; mt++)
                        asm volatile(
                            "mma.sync.aligned.m16n8k8.row.col.f32.tf32.tf32.f32 "
                            "{%0,%1,%2,%3}, {%4,%5,%6,%7}, {%8,%9}, {%0,%1,%2,%3};"
                            : "+f"(acc[mt][nt][0]), "+f"(acc[mt][nt][1]),
                              "+f"(acc[mt][nt][2]), "+f"(acc[mt][nt][3])
                            : "r"(a[mt][0]), "r"(a[mt][1]), "r"(a[mt][2]), "r"(a[mt][3]),
                              "r"(b0), "r"(b1));
                }
            }
        __syncthreads();
    }

    #pragma unroll
    for (int mt = 0; mt < 2; mt++) {
        int coA = co0 + cog * 32 + mt * 16 + grp;
        int coB = coA + 8;
        float bvA = BIAS ? bias[coA] : 0.f;
        float bvB = BIAS ? bias[coB] : 0.f;
        #pragma unroll
        for (int nt = 0; nt < 8; nt++) {
            int y = y0 + pxg * 2 + (nt >> 2);
            int x = x0 + (nt & 3) * 8 + tig * 2;
            float* pA = out + (((size_t)zz * Co + coA) * Hs + y) * Ws + x;
            float* pB = out + (((size_t)zz * Co + coB) * Hs + y) * Ws + x;
            *(float2*)pA = make_float2(acc[mt][nt][0] + bvA, acc[mt][nt][1] + bvA);
            *(float2*)pB = make_float2(acc[mt][nt][2] + bvB, acc[mt][nt][3] + bvB);
        }
    }
}

// ---------------- tf32 mma tap GEMM ----------------
// M[b][tap*CO+co][px] = sum_ci w[(ci*CO+co)*9+tap] * x[b][ci][px]
// 256 thr = 8 warps (2 co-groups x 4 px-groups); block = CO co x 256 px; grid (HW/256, 9, B).
template<int CO>
__global__ void __launch_bounds__(256) tap_gemm_mma(
        const float* __restrict__ x, const float* __restrict__ w,
        float* __restrict__ M, int Cin, int HW,
        const float* __restrict__ na, const float* __restrict__ nc) {
    const int MT = CO / 32;
    const int WSTR = CO + 8;
    __shared__ float Xs[8][264];
    __shared__ float Wss[8][WSTR];

    int px0 = blockIdx.x << 8;
    int tap = blockIdx.y;
    int b = blockIdx.z;
    int tid = threadIdx.x, lane = tid & 31, wid = tid >> 5;
    int cog = wid & 1, pxg = wid >> 1;
    int tig = lane & 3, grp = lane >> 2;

    float acc[MT][8][4] = {};
    const float* xb = x + (size_t)b * Cin * HW;

    for (int c0 = 0; c0 < Cin; c0 += 8) {
        for (int e = tid; e < 8 * 256; e += 256) {
            int k = e >> 8, px = e & 255;
            float v = xb[(size_t)(c0 + k) * HW + px0 + px];
            if (na) v = fmaf(na[b * Cin + c0 + k], v, nc[b * Cin + c0 + k]);
            Xs[k][px] = to_tf32(v);
        }
        for (int e = tid; e < 8 * CO; e += 256) {
            int k = e / CO, co = e - k * CO;
            Wss[k][co] = to_tf32(w[((size_t)(c0 + k) * CO + co) * 9 + tap]);
        }
        __syncthreads();

        uint32_t a[MT][4];
        #pragma unroll
        for (int mt = 0; mt < MT; mt++) {
            int cb = cog * MT * 16 + mt * 16;
            a[mt][0] = __float_as_uint(Wss[tig][cb + grp]);
            a[mt][1] = __float_as_uint(Wss[tig][cb + grp + 8]);
            a[mt][2] = __float_as_uint(Wss[tig + 4][cb + grp]);
            a[mt][3] = __float_as_uint(Wss[tig + 4][cb + grp + 8]);
        }
        #pragma unroll
        for (int nt = 0; nt < 8; nt++) {
            int px = pxg * 64 + nt * 8 + grp;
            uint32_t b0 = __float_as_uint(Xs[tig][px]);
            uint32_t b1 = __float_as_uint(Xs[tig + 4][px]);
            #pragma unroll
            for (int mt = 0; mt < MT; mt++)
                asm volatile(
                    "mma.sync.aligned.m16n8k8.row.col.f32.tf32.tf32.f32 "
                    "{%0,%1,%2,%3}, {%4,%5,%6,%7}, {%8,%9}, {%0,%1,%2,%3};"
                    : "+f"(acc[mt][nt][0]), "+f"(acc[mt][nt][1]),
                      "+f"(acc[mt][nt][2]), "+f"(acc[mt][nt][3])
                    : "r"(a[mt][0]), "r"(a[mt][1]), "r"(a[mt][2]), "r"(a[mt][3]),
                      "r"(b0), "r"(b1));
        }
        __syncthreads();
    }

    float* Mb = M + ((size_t)b * 9 + tap) * CO * HW;
    #pragma unroll
    for (int mt = 0; mt < MT; mt++) {
        int coA = cog * MT * 16 + mt * 16 + grp;
        int coB = coA + 8;
        float* rowA = Mb + (size_t)coA * HW + px0;
        float* rowB = Mb + (size_t)coB * HW + px0;
        #pragma unroll
        for (int nt = 0; nt < 8; nt++) {
            int px = pxg * 64 + nt * 8 + tig * 2;
            *(float2*)(rowA + px) = make_float2(acc[mt][nt][0], acc[mt][nt][1]);
            *(float2*)(rowB + px) = make_float2(acc[mt][nt][2], acc[mt][nt][3]);
        }
    }
}

// reduce 2 ci-split partials + bias
__global__ void reduce2_bias(const float* __restrict__ p, const float* __restrict__ bias,
                             float* __restrict__ out, int Co, int HW, int N) {
    int i = blockIdx.x * 256 + threadIdx.x;
    if (i >= N) return;
    int b = i / (Co * HW);
    int rem = i - b * Co * HW;
    int co = rem / HW;
    out[i] = p[(size_t)(2 * b) * Co * HW + rem] + p[(size_t)(2 * b + 1) * Co * HW + rem] + bias[co];
}

// ---------------- scalar 3x3 conv (final 3-channel layer only) ----------------
template<int CO_BLK, int PXH, bool BIAS>
__global__ void __launch_bounds__(128) conv3x3_v2(
        const float* __restrict__ in, const float* __restrict__ w,
        const float* __restrict__ bias, float* __restrict__ out,
        int Ci, int Co, int Hs, int Ws,
        const float* __restrict__ na, const float* __restrict__ nc) {
    const int TW = 32, TH = 8 * PXH;
    int tiles_x = Ws / TW;
    int tx0 = (blockIdx.x % tiles_x) * TW;
    int ty0 = (blockIdx.x / tiles_x) * TH;
    int co0 = blockIdx.y * CO_BLK;
    int b = blockIdx.z;
    int lx = threadIdx.x, ly = threadIdx.y;
    int tid = ly * 16 + lx;

    __shared__ float xs[TH + 2][TW + 4];
    __shared__ float ws_s[CO_BLK][9];

    float acc[CO_BLK][PXH][2];
    #pragma unroll
    for (int u = 0; u < CO_BLK; u++)
        #pragma unroll
        for (int r = 0; r < PXH; r++) { acc[u][r][0] = 0.f; acc[u][r][1] = 0.f; }

    const float* inb = in + (size_t)b * Ci * Hs * Ws;
    for (int ci = 0; ci < Ci; ci++) {
        const float* inc = inb + (size_t)ci * Hs * Ws;
        float aa = 1.f, cc0 = 0.f;
        if (na) { aa = na[b * Ci + ci]; cc0 = nc[b * Ci + ci]; }
        #pragma unroll 4
        for (int i = tid; i < (TH + 2) * (TW + 2); i += 128) {
            int r = i / (TW + 2), c = i % (TW + 2);
            int gy = ty0 + r - 1, gx = tx0 + c - 1;
            float v = 0.f;
            if ((unsigned)gy < (unsigned)Hs && (unsigned)gx < (unsigned)Ws)
                v = fmaf(aa, inc[gy * Ws + gx], cc0);
            xs[r][c] = v;
        }
        #pragma unroll
        for (int i = tid; i < CO_BLK * 9; i += 128)
            ws_s[i / 9][i % 9] = w[((size_t)(co0 + i / 9) * Ci + ci) * 9 + i % 9];
        __syncthreads();

        float xr[PXH + 2][4];
        #pragma unroll
        for (int r = 0; r < PXH + 2; r++)
            #pragma unroll
            for (int c = 0; c < 4; c++)
                xr[r][c] = xs[ly * PXH + r][2 * lx + c];

        #pragma unroll
        for (int u = 0; u < CO_BLK; u++) {
            #pragma unroll
            for (int i = 0; i < 3; i++)
                #pragma unroll
                for (int j = 0; j < 3; j++) {
                    float wv = ws_s[u][i * 3 + j];
                    #pragma unroll
                    for (int r = 0; r < PXH; r++) {
                        acc[u][r][0] = fmaf(xr[i + r][j],     wv, acc[u][r][0]);
                        acc[u][r][1] = fmaf(xr[i + r][j + 1], wv, acc[u][r][1]);
                    }
                }
        }
        __syncthreads();
    }

    int oy = ty0 + ly * PXH, ox = tx0 + 2 * lx;
    #pragma unroll
    for (int u = 0; u < CO_BLK; u++) {
        float bv = BIAS ? bias[co0 + u] : 0.f;
        #pragma unroll
        for (int r = 0; r < PXH; r++) {
            float* op = out + (((size_t)b * Co + co0 + u) * Hs + oy + r) * Ws + ox;
            *(float2*)op = make_float2(acc[u][r][0] + bv, acc[u][r][1] + bv);
        }
    }
}

// ---------------- 1x1 conv + residual, float4 ----------------
__global__ void conv1x1_res4(const float* __restrict__ x, const float* __restrict__ w,
                             const float* __restrict__ bias, float* __restrict__ out,
                             int Cc, int HW4) {
    int p = blockIdx.x * 128 + threadIdx.x;
    int o0 = blockIdx.y * 8;
    int b = blockIdx.z;
    __shared__ float ws[8 * 128];
    for (int i = threadIdx.x; i < 8 * Cc; i += 128)
        ws[i] = w[(o0 + i / Cc) * Cc + i % Cc];
    __syncthreads();
    const float4* xb = (const float4*)x + (size_t)b * Cc * HW4;
    float4 acc[8];
    #pragma unroll
    for (int u = 0; u < 8; u++) acc[u] = make_float4(0.f, 0.f, 0.f, 0.f);
    for (int ci = 0; ci < Cc; ci++) {
        float4 xv = xb[(size_t)ci * HW4 + p];
        #pragma unroll
        for (int u = 0; u < 8; u++) {
            float wv = ws[u * Cc + ci];
            acc[u].x = fmaf(wv, xv.x, acc[u].x);
            acc[u].y = fmaf(wv, xv.y, acc[u].y);
            acc[u].z = fmaf(wv, xv.z, acc[u].z);
            acc[u].w = fmaf(wv, xv.w, acc[u].w);
        }
    }
    float4* ob = (float4*)out + (size_t)b * Cc * HW4;
    #pragma unroll
    for (int u = 0; u < 8; u++) {
        float bv = bias[o0 + u];
        float4 rv = xb[(size_t)(o0 + u) * HW4 + p];
        float4 o;
        o.x = acc[u].x + bv + rv.x;
        o.y = acc[u].y + bv + rv.y;
        o.z = acc[u].z + bv + rv.z;
        o.w = acc[u].w + bv + rv.w;
        ob[(size_t)(o0 + u) * HW4 + p] = o;
    }
}

// ---------------- PAC gaussian kernel (channel-split capable) ----------------
__global__ void pac_K_part(const float* __restrict__ g, float* __restrict__ Kout,
                           float* __restrict__ Kpart, int Cg, int Hg, int Wg, int G) {
    int tiles_x = Wg / 16;
    int tx0 = (blockIdx.x % tiles_x) * 16, ty0 = (blockIdx.x / tiles_x) * 16;
    int gr = blockIdx.y, b = blockIdx.z;
    int cN = Cg / G, c0 = gr * cN;
    int lx = threadIdx.x, ly = threadIdx.y;
    int tid = ly * 16 + lx;
    __shared__ float gs[18][19];
    float acc[9];
    #pragma unroll
    for (int k = 0; k < 9; k++) acc[k] = 0.f;
    const float* gb = g + ((size_t)b * Cg + c0) * Hg * Wg;
    for (int c = 0; c < cN; c++) {
        const float* gc = gb + (size_t)c * Hg * Wg;
        #pragma unroll
        for (int i = tid; i < 18 * 18; i += 256) {
            int r = i / 18, cx = i % 18;
            int yy = ty0 + r - 1, xx = tx0 + cx - 1;
            gs[r][cx] = (yy >= 0 && yy < Hg && xx >= 0 && xx < Wg) ? gc[yy * Wg + xx] : 0.f;
        }
        __syncthreads();
        float ctr = gs[ly + 1][lx + 1];
        #pragma unroll
        for (int i = 0; i < 3; i++)
            #pragma unroll
            for (int j = 0; j < 3; j++) {
                float d = gs[ly + i][lx + j] - ctr;
                acc[i * 3 + j] = fmaf(d, d, acc[i * 3 + j]);
            }
        __syncthreads();
    }
    size_t px = (size_t)(ty0 + ly) * Wg + tx0 + lx;
    if (G == 1) {
        size_t base = (size_t)b * 9 * Hg * Wg + px;
        #pragma unroll
        for (int k = 0; k < 9; k++)
            Kout[base + (size_t)k * Hg * Wg] = __expf(-0.5f * acc[k]);
    } else {
        size_t base = ((size_t)(b * G + gr) * 9) * Hg * Wg + px;
        #pragma unroll
        for (int k = 0; k < 9; k++)
            Kpart[base + (size_t)k * Hg * Wg] = acc[k];
    }
}

__global__ void pac_K_comb(const float* __restrict__ Kpart, float* __restrict__ K,
                           int G, int planes9HW, int N) {
    int i = blockIdx.x * 256 + threadIdx.x;
    if (i >= N) return;
    int b = i / planes9HW;
    int rem = i - b * planes9HW;
    float s = 0.f;
    const float* p = Kpart + (size_t)b * G * planes9HW + rem;
    for (int gr = 0; gr < G; gr++) s += p[(size_t)gr * planes9HW];
    K[i] = __expf(-0.5f * s);
}

// ---------------- PAC combine ----------------
template<int CO_T>
__global__ void pac_combine(const float* __restrict__ M, const float* __restrict__ K,
                            const float* __restrict__ bias, float* __restrict__ out,
                            int Co, int Hs, int Ws) {
    int Ho = 2 * Hs, Wo = 2 * Ws;
    int px = blockIdx.x * 256 + threadIdx.x;
    int h = px / Wo, w = px % Wo;
    int co0 = blockIdx.y * CO_T;
    int b = blockIdx.z;

    float acc[CO_T];
    #pragma unroll
    for (int u = 0; u < CO_T; u++) acc[u] = bias[co0 + u];

    int nr, ry[2], rk[2];
    if (h & 1) {
        nr = 2; rk[0] = 0; ry[0] = (h - 1) >> 1; rk[1] = 2; ry[1] = (h + 1) >> 1;
        if (ry[1] >= Hs) nr = 1;
    } else { nr = 1; rk[0] = 1; ry[0] = h >> 1; }
    int ncn, cx[2], ck[2];
    if (w & 1) {
        ncn = 2; ck[0] = 0; cx[0] = (w - 1) >> 1; ck[1] = 2; cx[1] = (w + 1) >> 1;
        if (cx[1] >= Ws) ncn = 1;
    } else { ncn = 1; ck[0] = 1; cx[0] = w >> 1; }

    const float* Kb = K + (size_t)b * 9 * Ho * Wo + px;
    const float* Mb = M + (size_t)b * 9 * Co * Hs * Ws;
    int HsWs = Hs * Ws;
    for (int rr = 0; rr < nr; rr++)
        for (int cc = 0; cc < ncn; cc++) {
            int k = rk[rr] * 3 + ck[cc];
            float Kv = __ldg(Kb + (size_t)k * Ho * Wo);
            const float* Mp = Mb + ((size_t)k * Co + co0) * HsWs + ry[rr] * Ws + cx[cc];
            #pragma unroll
            for (int u = 0; u < CO_T; u++)
                acc[u] = fmaf(Kv, __ldg(Mp + (size_t)u * HsWs), acc[u]);
        }
    #pragma unroll
    for (int u = 0; u < CO_T; u++)
        out[(((size_t)b * Co + co0 + u) * Ho + h) * Wo + w] = acc[u];
}

// ---------------- driver ----------------
extern "C" void kernel_launch(void* const* d_in, const int* in_sizes, int n_in,
                              void* d_out, int out_size) {
    const float* x      = (const float*)d_in[0];
    const float* ef2    = (const float*)d_in[1];
    const float* ef1    = (const float*)d_in[2];
    const float* W_down = (const float*)d_in[3];
    const float* b_down = (const float*)d_in[4];
    const float* W_mid  = (const float*)d_in[5];
    const float* b_mid  = (const float*)d_in[6];
    const float* W_adj2 = (const float*)d_in[7];
    const float* b_adj2 = (const float*)d_in[8];
    const float* W_adj1 = (const float*)d_in[9];
    const float* b_adj1 = (const float*)d_in[10];
    const float* W16    = (const float*)d_in[11];
    const float* b16    = (const float*)d_in[12];
    const float* W20    = (const float*)d_in[13];
    const float* b20    = (const float*)d_in[14];
    const float* W24    = (const float*)d_in[15];
    const float* b24    = (const float*)d_in[16];
    float* out = (float*)d_out;

    float *t1, *part, *t2, *g2, *K1, *Kp, *M1, *y1, *g1, *K2, *M2, *y2, *na, *nc;
    cudaGetSymbolAddress((void**)&t1, g_t1);
    cudaGetSymbolAddress((void**)&part, g_part);
    cudaGetSymbolAddress((void**)&t2, g_t2);
    cudaGetSymbolAddress((void**)&g2, g_g2);
    cudaGetSymbolAddress((void**)&K1, g_K1);
    cudaGetSymbolAddress((void**)&Kp, g_Kp);
    cudaGetSymbolAddress((void**)&M1, g_M1);
    cudaGetSymbolAddress((void**)&y1, g_y1);
    cudaGetSymbolAddress((void**)&g1, g_g1);
    cudaGetSymbolAddress((void**)&K2, g_K2);
    cudaGetSymbolAddress((void**)&M2, g_M2);
    cudaGetSymbolAddress((void**)&y2, g_y2);
    cudaGetSymbolAddress((void**)&na, g_na);
    cudaGetSymbolAddress((void**)&nc, g_nc);

    dim3 cblk(16, 8);
    dim3 blk16(16, 16);

    // 1) inorm(x) coefficients
    stats_coef<0><<<512, 256>>>(x, 64 * 64, na, nc);

    // 2) conv_down 256->128 @64x64 (tf32 mma, norm fused, ci-split 2), then reduce+bias
    conv3x3_mma2<2, false><<<dim3(16, 2, 4), 256>>>(x, W_down, b_down, part,
                                                    256, 128, 64, 64, na, nc);
    reduce2_bias<<<4096, 256>>>(part, b_down, t1, 128, 64 * 64, 2 * 128 * 64 * 64);

    // 3) 1x1 + residual
    conv1x1_res4<<<dim3(8, 16, 2), 128>>>(t1, W_mid, b_mid, t2, 128, 1024);

    // 4) g2 = adjust_ef_lv2: 64->128 @128x128 (tf32 mma)
    conv3x3_mma2<1, true><<<dim3(64, 2, 2), 256>>>(ef2, W_adj2, b_adj2, g2,
                                                   64, 128, 128, 128,
                                                   (const float*)0, (const float*)0);

    // 5) PAC kernel 1 (channel split G=4 + combine)
    pac_K_part<<<dim3(64, 4, 2), blk16>>>(g2, K1, Kp, 128, 128, 128, 4);
    pac_K_comb<<<1152, 256>>>(Kp, K1, 4, 9 * 128 * 128, 2 * 9 * 128 * 128);

    // 6) pacT1 = tf32 tap GEMM + combine
    tap_gemm_mma<64><<<dim3(16, 9, 2), 256>>>(t2, W16, M1, 128, 4096,
                                              (const float*)0, (const float*)0);
    pac_combine<8><<<dim3(64, 8, 2), 256>>>(M1, K1, b16, y1, 64, 64, 64);

    // 7) dinorm coefs for y1
    stats_coef<1><<<128, 256>>>(y1, 128 * 128, na, nc);

    // 8) g1 = adjust_ef_lv1: 32->64 @256x256 (tf32 mma)
    conv3x3_mma2<1, true><<<dim3(256, 1, 2), 256>>>(ef1, W_adj1, b_adj1, g1,
                                                    32, 64, 256, 256,
                                                    (const float*)0, (const float*)0);

    // 9) PAC kernel 2 (direct)
    pac_K_part<<<dim3(256, 1, 2), blk16>>>(g1, K2, Kp, 64, 256, 256, 1);

    // 10) pacT2 = tf32 tap GEMM (y1 affine fused) + combine
    tap_gemm_mma<32><<<dim3(64, 9, 2), 256>>>(y1, W20, M2, 64, 16384, na, nc);
    pac_combine<8><<<dim3(256, 4, 2), 256>>>(M2, K2, b20, y2, 32, 128, 128);

    // 11) dinorm coefs for y2
    stats_coef<1><<<64, 256>>>(y2, 256 * 256, na, nc);

    // 12) final conv 32->3 @256x256 (y2 affine fused, scalar)
    conv3x3_v2<3, 2, true><<<dim3(128, 1, 2), cblk>>>(y2, W24, b24, out,
                                                      32, 3, 256, 256, na, nc);
}